// round 17
// baseline (speedup 1.0000x reference)
#include <cuda_runtime.h>
#include <cuda_fp16.h>
#include <math.h>
#include <stdint.h>

#define STRIDE 152                  // fp16 elems per tile row (incl. ip cols + pad)
#define NT 512
// ---- smem byte offsets ----
#define TSH 0
#define TSL 19456
#define TDH 38912
#define TDL 58368
#define TXH 77824
#define TXL 97280
#define RING0 116736
#define RING1 153600
#define SMW_NTC 190464              // ntc frag hi (4096)
#define SMW_MP2 194560              // mp2 frag hi (4096)
#define BIA_B 207872                // 928 floats
#define SCO_B 211584                // 64x8 f32
#define GST_B 213632                // 256 f32
#define SCS_B 214656                // 64x16 f32
#define DCS_B 218752
#define M16_B 222848
#define SMEM_BYTES 226944

// ---- gmem weight buffer layout (fp16 hi-only fragments) ----
__device__ float g_b1[128];
__device__ __align__(128) unsigned char g_wb[274432];

// ---------- helpers ----------
__device__ __forceinline__ uint32_t smem_u32(const void* p) {
    uint32_t a;
    asm("{ .reg .u64 t; cvta.to.shared.u64 t, %1; cvt.u32.u64 %0, t; }" : "=r"(a) : "l"(p));
    return a;
}
template<int N> __device__ __forceinline__ void cp_wait() {
    asm volatile("cp.async.wait_group %0;" :: "n"(N));
}
__device__ __forceinline__ void stage_fn(uint32_t dsm, uint64_t gsrc, int bytes, int tid) {
    for (int o = tid * 16; o < bytes; o += NT * 16)
        asm volatile("cp.async.cg.shared.global [%0], [%1], 16;" :: "r"(dsm + o), "l"(gsrc + o) : "memory");
    asm volatile("cp.async.commit_group;" ::: "memory");
}
__device__ __forceinline__ void mma16816(float* c, uint32_t a0, uint32_t a1, uint32_t a2, uint32_t a3,
                                         uint32_t b0, uint32_t b1) {
    asm volatile("mma.sync.aligned.m16n8k16.row.col.f32.f16.f16.f32 "
                 "{%0,%1,%2,%3}, {%4,%5,%6,%7}, {%8,%9}, {%0,%1,%2,%3};"
                 : "+f"(c[0]), "+f"(c[1]), "+f"(c[2]), "+f"(c[3])
                 : "r"(a0), "r"(a1), "r"(a2), "r"(a3), "r"(b0), "r"(b1));
}
#define LDSM4(r0, r1, r2, r3, addr) \
    asm volatile("ldmatrix.sync.aligned.m8n8.x4.shared.b16 {%0,%1,%2,%3}, [%4];" \
                 : "=r"(r0), "=r"(r1), "=r"(r2), "=r"(r3) : "r"(addr))

__device__ __host__ __forceinline__ uint32_t frag_off(int k, int n, int ntiles) {
    int kt = k >> 4, kk = k & 15;
    int reg = kk >> 3, r8 = kk & 7, m = r8 >> 1, half = r8 & 1;
    int nt = n >> 3, ln = (n & 7) * 4 + m;
    return (uint32_t)((kt * ntiles + nt) * 32 + ln) * 8u + (uint32_t)reg * 4u + (uint32_t)half * 2u;
}
__device__ __forceinline__ uint32_t pack_h2(float a, float b) {
    __half2 t;
    t.x = __float2half_rn(a);
    t.y = __float2half_rn(b);
    return *(uint32_t*)&t;
}
__device__ __forceinline__ void split_h(float v, float& hi, float& lo) {
    __half h = __float2half_rn(v);
    hi = __half2float(h);
    lo = v - hi;
}

// ---------- merged prep kernel ----------
struct PrepAll {
    const float *npW, *npb, *epW, *epb, *im1W, *im1b;
    const float *im2W, *mp1W, *qW, *kW, *vW, *outW, *ctoW, *mp2W, *ntcW;
};

__global__ void prep_all(PrepAll pp)
{
    __shared__ float red[1024];
    if (blockIdx.x < 128) {
        const int i = blockIdx.x;
        const int o = threadIdx.x & 127, q = threadIdx.x >> 7;
        float s1 = 0.f, s2 = 0.f;
#pragma unroll 8
        for (int h = q * 32; h < q * 32 + 32; ++h) {
            s1 = fmaf(__ldg(pp.npW + i * 128 + h), __ldg(pp.im1W + h * 128 + o), s1);
            s2 = fmaf(__ldg(pp.epW + i * 128 + h), __ldg(pp.im1W + (128 + h) * 128 + o), s2);
        }
        red[q * 128 + o] = s1;
        red[512 + q * 128 + o] = s2;
        __syncthreads();
        if (q == 0) {
            float a1 = red[o] + red[128 + o] + red[256 + o] + red[384 + o];
            float a2 = red[512 + o] + red[640 + o] + red[768 + o] + red[896 + o];
            uint32_t off = frag_off(i, o, 16);
            *(__half*)(g_wb + off)          = __float2half_rn(a1);
            *(__half*)(g_wb + 32768 + off)  = __float2half_rn(a2);
            if (i == 0) {
                float sb = pp.im1b[o];
#pragma unroll 8
                for (int h = 0; h < 128; ++h)
                    sb += pp.npb[h] * pp.im1W[h * 128 + o] + pp.epb[h] * pp.im1W[(128 + h) * 128 + o];
                g_b1[o] = sb;
            }
        }
        return;
    }
    const int b = blockIdx.x - 126;       // 2..9
    if (b < 7) {
        const float* W = nullptr;
        switch (b) { case 2: W = pp.im2W; break; case 3: W = pp.mp1W; break;
                     case 4: W = pp.qW; break; case 5: W = pp.kW; break;
                     case 6: W = pp.vW; break; default: break; }
        unsigned char* base = g_wb + b * 32768;
        for (int idx = threadIdx.x; idx < 16384; idx += blockDim.x) {
            int k = idx >> 7, n = idx & 127;
            *(__half*)(base + frag_off(k, n, 16)) = __float2half_rn(W[idx]);
        }
    } else if (b == 7) {
        unsigned char* base = g_wb + 229376;
        for (int idx = threadIdx.x; idx < 144 * 128; idx += blockDim.x) {
            int k = idx >> 7, n = idx & 127;
            float v = (k < 128) ? pp.outW[k * 128 + n] : pp.ctoW[(k - 128) * 128 + n];
            *(__half*)(base + frag_off(k, n, 16)) = __float2half_rn(v);
        }
    } else {
        const float* W = (b == 8) ? pp.ntcW : pp.mp2W;
        unsigned char* base = g_wb + ((b == 8) ? 266240 : 270336);
        for (int idx = threadIdx.x; idx < 2048; idx += blockDim.x) {
            int k = idx >> 4, n = idx & 15;
            *(__half*)(base + frag_off(k, n, 2)) = __float2half_rn(W[idx]);
        }
    }
}

// ---------- GEMM pieces (warp tile 16x32; wm in {0..3}, wn in {0..3}) ----------
// 2-pass fused (A hi+lo share B fragments)
template<int NKT>
__device__ __forceinline__ void gemm_f(float (&acc)[4][4], uint32_t aH, uint32_t aL,
                                       const char* slot, int wn, int lane)
{
#pragma unroll
    for (int kt = 0; kt < NKT; ++kt) {
        uint32_t ah[4], al[4];
        LDSM4(ah[0], ah[1], ah[2], ah[3], aH + kt * 32);
        LDSM4(al[0], al[1], al[2], al[3], aL + kt * 32);
        const char* Bp = slot + ((kt * 16 + wn * 4) * 32 + lane) * 8;
#pragma unroll
        for (int nt = 0; nt < 4; ++nt) {
            uint2 b = *(const uint2*)(Bp + nt * 256);
            mma16816(acc[nt], ah[0], ah[1], ah[2], ah[3], b.x, b.y);
            mma16816(acc[nt], al[0], al[1], al[2], al[3], b.x, b.y);
        }
    }
}
// 1-pass (A-hi only) — damped paths (metric chain, Q, K)
template<int NKT>
__device__ __forceinline__ void gemm_1(float (&acc)[4][4], uint32_t aH,
                                       const char* slot, int wn, int lane)
{
#pragma unroll
    for (int kt = 0; kt < NKT; ++kt) {
        uint32_t ah[4];
        LDSM4(ah[0], ah[1], ah[2], ah[3], aH + kt * 32);
        const char* Bp = slot + ((kt * 16 + wn * 4) * 32 + lane) * 8;
#pragma unroll
        for (int nt = 0; nt < 4; ++nt) {
            uint2 b = *(const uint2*)(Bp + nt * 256);
            mma16816(acc[nt], ah[0], ah[1], ah[2], ah[3], b.x, b.y);
        }
    }
}
__device__ __forceinline__ void small_pass(float (&acc)[2][4], uint32_t aaddr, const char* slot,
                                           int lane)
{
#pragma unroll
    for (int kt = 0; kt < 8; ++kt) {
        uint32_t a0, a1, a2, a3;
        LDSM4(a0, a1, a2, a3, aaddr + kt * 32);
        const char* Bp = slot + (kt * 2 * 32 + lane) * 8;
#pragma unroll
        for (int nt = 0; nt < 2; ++nt) {
            uint2 b = *(const uint2*)(Bp + nt * 256);
            mma16816(acc[nt], a0, a1, a2, a3, b.x, b.y);
        }
    }
}
__device__ __forceinline__ void zero16(float (&a)[4][4]) {
#pragma unroll
    for (int i = 0; i < 4; ++i)
#pragma unroll
        for (int j = 0; j < 4; ++j) a[i][j] = 0.f;
}
// hi-only activation store
__device__ __forceinline__ void store_tile_h(const float (&acc)[4][4], char* SM, int tH,
                                             const float* bias, int wm, int wn, int lane)
{
    const int r1 = wm * 16 + (lane >> 2), r2 = r1 + 8;
    const int m2 = (lane & 3) * 2;
#pragma unroll
    for (int nt = 0; nt < 4; ++nt) {
        int cb = wn * 32 + nt * 8 + m2;
        float b0 = bias[cb], b1 = bias[cb + 1];
        float v0 = fmaxf(acc[nt][0] + b0, 0.f), v1 = fmaxf(acc[nt][1] + b1, 0.f);
        float v2 = fmaxf(acc[nt][2] + b0, 0.f), v3 = fmaxf(acc[nt][3] + b1, 0.f);
        *(uint32_t*)(SM + tH + (r1 * STRIDE + cb) * 2) = pack_h2(v0, v1);
        *(uint32_t*)(SM + tH + (r2 * STRIDE + cb) * 2) = pack_h2(v2, v3);
    }
}
__device__ __forceinline__ void store_small(const float (&acc)[2][4], float* out,
                                            const float* bias, bool dot, int wm4, int lane)
{
    const int r1 = wm4 * 16 + (lane >> 2), r2 = r1 + 8;
    const int m2 = (lane & 3) * 2;
#pragma unroll
    for (int nt = 0; nt < 2; ++nt) {
        int c = nt * 8 + m2;
        float b0 = bias[c], b1 = bias[c + 1];
        float v0 = acc[nt][0] + b0, v1 = acc[nt][1] + b1;
        float v2 = acc[nt][2] + b0, v3 = acc[nt][3] + b1;
        if (dot) { v0 = tanhf(v0); v1 = tanhf(v1); v2 = tanhf(v2); v3 = tanhf(v3); }
        *(float2*)(out + r1 * 16 + c) = make_float2(v0, v1);
        *(float2*)(out + r2 * 16 + c) = make_float2(v2, v3);
    }
}
__device__ __forceinline__ void convert_tile(char* SM, int tH, int tL,
                                             const float* __restrict__ g, int rows, int tid)
{
#pragma unroll
    for (int i = 0; i < 4; ++i) {
        int f4 = tid + i * NT;
        int r = f4 >> 5, c4 = (f4 & 31) << 2;
        float4 v = make_float4(0.f, 0.f, 0.f, 0.f);
        if (r < rows) v = *(const float4*)(g + (size_t)r * 128 + c4);
        float h0, l0, h1, l1, h2, l2, h3, l3;
        split_h(v.x, h0, l0); split_h(v.y, h1, l1);
        split_h(v.z, h2, l2); split_h(v.w, h3, l3);
        uint2 uh, ul;
        uh.x = pack_h2(h0, h1); uh.y = pack_h2(h2, h3);
        ul.x = pack_h2(l0, l1); ul.y = pack_h2(l2, l3);
        *(uint2*)(SM + tH + (r * STRIDE + c4) * 2) = uh;
        *(uint2*)(SM + tL + (r * STRIDE + c4) * 2) = ul;
    }
}
__device__ __forceinline__ void convert_tile_h(char* SM, int tH,
                                               const float* __restrict__ g, int rows, int tid)
{
#pragma unroll
    for (int i = 0; i < 4; ++i) {
        int f4 = tid + i * NT;
        int r = f4 >> 5, c4 = (f4 & 31) << 2;
        float4 v = make_float4(0.f, 0.f, 0.f, 0.f);
        if (r < rows) v = *(const float4*)(g + (size_t)r * 128 + c4);
        uint2 uh;
        uh.x = pack_h2(v.x, v.y); uh.y = pack_h2(v.z, v.w);
        *(uint2*)(SM + tH + (r * STRIDE + c4) * 2) = uh;
    }
}

struct Params {
    const float *src, *dst, *edge;
    const float *im2b, *mp1b, *mp2b, *qb, *kb, *vb, *ntcb, *ctob, *outb;
    float* out;
    int B;
};

__global__ __launch_bounds__(NT, 1) void fused_kernel(Params p)
{
    extern __shared__ __align__(16) char SM[];
    const int tid = threadIdx.x, lane = tid & 31, wid = tid >> 5;
    const int wm = wid & 3, wn = wid >> 2;          // 16 warps: 4 row x 4 col groups
    const int wm4 = wid & 3, wn2 = wid >> 2;        // small-GEMM mapping
    const int row0 = blockIdx.x * 64;
    const int rows = min(64, p.B - row0);
    const uint32_t sbase = smem_u32(SM);
    const uint64_t gaddr = (uint64_t)__cvta_generic_to_global((void*)g_wb);
    float* BIA = (float*)(SM + BIA_B);
    float* SCO = (float*)(SM + SCO_B);
    float* GST = (float*)(SM + GST_B);

    // per-thread ldmatrix base offsets (row = lane&15, col-half = lane>>4)
    const uint32_t aoff  = sbase + (uint32_t)(((wm * 16 + (lane & 15)) * STRIDE + ((lane >> 4) & 1) * 8) * 2);
    const uint32_t aoffS = aoff;    // identical mapping for small GEMMs

#define STAGE(slot, goff, bytes) stage_fn(sbase + (slot), gaddr + (goff), (bytes), tid)

    STAGE(SMW_NTC, 266240, 8192);           // ntc + mp2 frags (contiguous)
    STAGE(RING0, 0, 32768);                 // A1

    if (tid < 128) {
        BIA[tid] = g_b1[tid];          BIA[128 + tid] = p.im2b[tid];
        BIA[256 + tid] = p.mp1b[tid];  BIA[384 + tid] = p.qb[tid];
        BIA[512 + tid] = p.kb[tid];    BIA[640 + tid] = p.vb[tid];
        BIA[768 + tid] = p.outb[tid] + p.ctob[tid];
    }
    if (tid < 16) { BIA[896 + tid] = p.mp2b[tid]; BIA[912 + tid] = p.ntcb[tid]; }
    if (tid < 256) {   // geometric-product sign table (MSB-first bit convention)
        int i = tid >> 4, j = tid & 15;
        float s = 1.f;
#pragma unroll
        for (int k = 0; k < 4; ++k)
            if ((j >> (3 - k)) & 1)
                if (__popc(i >> (4 - k)) & 1) s = -s;
        GST[tid] = s;
    }
    convert_tile(SM, TSH, TSL, p.src + (size_t)row0 * 128, rows, tid);
    convert_tile_h(SM, TXH, p.edge + (size_t)row0 * 128, rows, tid);
    convert_tile(SM, TDH, TDL, p.dst + (size_t)row0 * 128, rows, tid);
    cp_wait<1>();
    __syncthreads();                        // small weights + tiles ready

    // ---- sc (warps 0-3) / dc (warps 4-7): 128->16, 2-pass ----
    if (wn2 < 2) {
        float a2[2][4] = {};
        const uint32_t aH = aoffS + ((wn2 == 0) ? TSH : TDH);
        const uint32_t aL = aoffS + ((wn2 == 0) ? TSL : TDL);
        small_pass(a2, aH, SM + SMW_NTC, lane);
        small_pass(a2, aL, SM + SMW_NTC, lane);
        store_small(a2, (float*)(SM + ((wn2 == 0) ? SCS_B : DCS_B)), BIA + 912, false, wm4, lane);
    }

    float acc[4][4];
    zero16(acc);
    // ---- G1: h1 = relu(src@A1 + edge@A2 + b1) — 1-pass ----
    STAGE(RING1, 32768, 32768);  cp_wait<1>(); __syncthreads();
    gemm_1<8>(acc, aoff + TSH, SM + RING0, wn, lane);
    __syncthreads();
    STAGE(RING0, 65536, 32768);  cp_wait<1>(); __syncthreads();
    gemm_1<8>(acc, aoff + TXH, SM + RING1, wn, lane);
    __syncthreads();
    store_tile_h(acc, SM, TXH, BIA + 0, wm, wn, lane);
    __syncthreads();

    // ---- G2: h2 = relu(h1@im2) — 1-pass ----
    zero16(acc);
    STAGE(RING1, 98304, 32768);  cp_wait<1>(); __syncthreads();
    gemm_1<8>(acc, aoff + TXH, SM + RING0, wn, lane);
    __syncthreads();
    store_tile_h(acc, SM, TXH, BIA + 128, wm, wn, lane);
    __syncthreads();

    // ---- G3: h3 = relu(h2@mp1) — 1-pass ----
    zero16(acc);
    STAGE(RING0, 131072, 32768); cp_wait<1>(); __syncthreads();
    gemm_1<8>(acc, aoff + TXH, SM + RING1, wn, lane);
    __syncthreads();
    store_tile_h(acc, SM, TXH, BIA + 256, wm, wn, lane);
    __syncthreads();

    // ---- m16 = tanh(h3@mp2 + b) (warps 0-3), 1-pass ----
    if (wn2 == 0) {
        float a2[2][4] = {};
        small_pass(a2, aoffS + TXH, SM + SMW_MP2, lane);
        store_small(a2, (float*)(SM + M16_B), BIA + 896, true, wm4, lane);
    }
    __syncthreads();

    // ---- clifford: metric + adapted inner product -> ip into TX cols 128..143 ----
    if (tid < 64) {
        const float* M16 = (float*)(SM + M16_B);
        const float* SCS = (float*)(SM + SCS_B);
        const float* DCS = (float*)(SM + DCS_B);
        int r = tid;
        float m[16], s[16], d[16];
#pragma unroll
        for (int k = 0; k < 16; ++k) {
            m[k] = M16[r * 16 + k];
            s[k] = SCS[r * 16 + k];
            d[k] = DCS[r * 16 + k];
        }
        float L[4][4];
#pragma unroll
        for (int a = 0; a < 4; ++a)
#pragma unroll
            for (int b = 0; b < 4; ++b) {
                float mv = m[a * 4 + b];
                L[a][b] = (a > b) ? mv : (a == b) ? (log1pf(expf(mv)) + 1e-6f) : 0.f;
            }
        float met[4][4];
#pragma unroll
        for (int a = 0; a < 4; ++a)
#pragma unroll
            for (int b = 0; b < 4; ++b) {
                float q = 0.f;
#pragma unroll
                for (int c = 0; c < 4; ++c) q = fmaf(L[a][c], L[b][c], q);
                met[a][b] = q;
            }
        const int VI[4] = {1, 2, 4, 8};
        float sv[4], dv[4];
#pragma unroll
        for (int a = 0; a < 4; ++a) {
            float qs = 0.f, qd = 0.f;
#pragma unroll
            for (int b = 0; b < 4; ++b) {
                qs = fmaf(met[a][b], s[VI[b]], qs);
                qd = fmaf(met[a][b], d[VI[b]], qd);
            }
            sv[a] = qs; dv[a] = qd;
        }
#pragma unroll
        for (int a = 0; a < 4; ++a) { s[VI[a]] = sv[a]; d[VI[a]] = dv[a]; }
#pragma unroll
        for (int k = 0; k < 16; ++k) {
            float q = 0.f;
#pragma unroll
            for (int i = 0; i < 16; ++i) {
                int j = i ^ k;
                q = fmaf(GST[i * 16 + j], fmaf(s[i], d[j], d[i] * s[j]), q);
            }
            float ip = 0.5f * q, h, l;
            split_h(ip, h, l);
            *(__half*)(SM + TXH + (r * STRIDE + 128 + k) * 2) = __float2half_rn(h);
            *(__half*)(SM + TXL + (r * STRIDE + 128 + k) * 2) = __float2half_rn(l);
        }
    }
    __syncthreads();

    // ---- Q = src@qW (kept in registers), 1-pass ----
    float accQ[4][4];
    zero16(accQ);
    STAGE(RING1, 163840, 32768); cp_wait<1>(); __syncthreads();
    gemm_1<8>(accQ, aoff + TSH, SM + RING0, wn, lane);
    __syncthreads();

    // ---- K = dst@kW, 1-pass ----
    float accK[4][4];
    zero16(accK);
    STAGE(RING0, 196608, 32768); cp_wait<1>(); __syncthreads();
    gemm_1<8>(accK, aoff + TDH, SM + RING1, wn, lane);

    // ---- scores = (Q+qb).(K+kb)/4 per head (enh cancels in softmax) ----
    {
        const int rb = wm * 16 + (lane >> 2);
        const int m = lane & 3, m2 = m * 2;
#pragma unroll
        for (int e = 0; e < 2; ++e) {
            float pa = 0.f, pb = 0.f;
#pragma unroll
            for (int u = 0; u < 2; ++u) {
                int nt = 2 * e + u, cb = wn * 32 + nt * 8 + m2;
                float qb0 = BIA[384 + cb], qb1 = BIA[384 + cb + 1];
                float kb0 = BIA[512 + cb], kb1 = BIA[512 + cb + 1];
                pa += (accQ[nt][0] + qb0) * (accK[nt][0] + kb0)
                    + (accQ[nt][1] + qb1) * (accK[nt][1] + kb1);
                pb += (accQ[nt][2] + qb0) * (accK[nt][2] + kb0)
                    + (accQ[nt][3] + qb1) * (accK[nt][3] + kb1);
            }
            pa += __shfl_xor_sync(0xFFFFFFFFu, pa, 1);
            pa += __shfl_xor_sync(0xFFFFFFFFu, pa, 2);
            pb += __shfl_xor_sync(0xFFFFFFFFu, pb, 1);
            pb += __shfl_xor_sync(0xFFFFFFFFu, pb, 2);
            if (m == 0) {
                int h = wn * 2 + e;
                SCO[rb * 8 + h]       = 0.25f * pa;
                SCO[(rb + 8) * 8 + h] = 0.25f * pb;
            }
        }
    }
    __syncthreads();
    if (tid < 64) {
        float s0[8], mx = -1e30f;
#pragma unroll
        for (int h = 0; h < 8; ++h) { s0[h] = SCO[tid * 8 + h]; mx = fmaxf(mx, s0[h]); }
        float sum = 0.f;
#pragma unroll
        for (int h = 0; h < 8; ++h) { s0[h] = expf(s0[h] - mx); sum += s0[h]; }
        float inv = 1.f / sum;
#pragma unroll
        for (int h = 0; h < 8; ++h) SCO[tid * 8 + h] = s0[h] * inv;
    }
    __syncthreads();

    // ---- V = dst@vW ; att = w8*(V+vb) -> TX, 2-pass (direct path) ----
    zero16(acc);
    STAGE(RING1, 229376, 36864); cp_wait<1>(); __syncthreads();
    gemm_f<8>(acc, aoff + TDH, aoff + TDL, SM + RING0, wn, lane);
    __syncthreads();
    {
        const int r1 = wm * 16 + (lane >> 2), r2 = r1 + 8;
        const int m2 = (lane & 3) * 2;
#pragma unroll
        for (int nt = 0; nt < 4; ++nt) {
            int cb = wn * 32 + nt * 8 + m2;
            int h = wn * 2 + (nt >> 1);
            float w1 = SCO[r1 * 8 + h], w2 = SCO[r2 * 8 + h];
            float b0 = BIA[640 + cb], b1 = BIA[640 + cb + 1];
            float v0 = (acc[nt][0] + b0) * w1, v1 = (acc[nt][1] + b1) * w1;
            float v2 = (acc[nt][2] + b0) * w2, v3 = (acc[nt][3] + b1) * w2;
            float h0, l0, h1, l1;
            split_h(v0, h0, l0); split_h(v1, h1, l1);
            *(uint32_t*)(SM + TXH + (r1 * STRIDE + cb) * 2) = pack_h2(h0, h1);
            *(uint32_t*)(SM + TXL + (r1 * STRIDE + cb) * 2) = pack_h2(l0, l1);
            split_h(v2, h0, l0); split_h(v3, h1, l1);
            *(uint32_t*)(SM + TXH + (r2 * STRIDE + cb) * 2) = pack_h2(h0, h1);
            *(uint32_t*)(SM + TXL + (r2 * STRIDE + cb) * 2) = pack_h2(l0, l1);
        }
    }
    __syncthreads();

    // ---- out = [att|ip]@[outW;ctoW] + (outb+ctob), 9 k-tiles, 2-pass ----
    zero16(acc);
    cp_wait<0>(); __syncthreads();
    gemm_f<9>(acc, aoff + TXH, aoff + TXL, SM + RING1, wn, lane);
    {
        const int r1 = wm * 16 + (lane >> 2), r2 = r1 + 8;
        const int m2 = (lane & 3) * 2;
#pragma unroll
        for (int nt = 0; nt < 4; ++nt) {
            int cb = wn * 32 + nt * 8 + m2;
            float b0 = BIA[768 + cb], b1 = BIA[768 + cb + 1];
            if (r1 < rows)
                *(float2*)(p.out + (size_t)(row0 + r1) * 128 + cb) =
                    make_float2(acc[nt][0] + b0, acc[nt][1] + b1);
            if (r2 < rows)
                *(float2*)(p.out + (size_t)(row0 + r2) * 128 + cb) =
                    make_float2(acc[nt][2] + b0, acc[nt][3] + b1);
        }
    }
}

// ---------- launch ----------
extern "C" void kernel_launch(void* const* d_in, const int* in_sizes, int n_in,
                              void* d_out, int out_size)
{
    Params p;
    p.src = (const float*)d_in[0];
    p.dst = (const float*)d_in[1];
    p.edge = (const float*)d_in[2];
    p.im2b = (const float*)d_in[10];
    p.mp1b = (const float*)d_in[12];
    p.mp2b = (const float*)d_in[14];
    p.qb   = (const float*)d_in[16];
    p.kb   = (const float*)d_in[18];
    p.vb   = (const float*)d_in[20];
    p.ntcb = (const float*)d_in[22];
    p.ctob = (const float*)d_in[24];
    p.outb = (const float*)d_in[26];
    p.out = (float*)d_out;
    p.B = in_sizes[0] / 128;

    PrepAll pa;
    pa.npW  = (const float*)d_in[3];
    pa.npb  = (const float*)d_in[4];
    pa.epW  = (const float*)d_in[5];
    pa.epb  = (const float*)d_in[6];
    pa.im1W = (const float*)d_in[7];
    pa.im1b = (const float*)d_in[8];
    pa.im2W = (const float*)d_in[9];
    pa.mp1W = (const float*)d_in[11];
    pa.qW   = (const float*)d_in[15];
    pa.kW   = (const float*)d_in[17];
    pa.vW   = (const float*)d_in[19];
    pa.outW = (const float*)d_in[25];
    pa.ctoW = (const float*)d_in[23];
    pa.mp2W = (const float*)d_in[13];
    pa.ntcW = (const float*)d_in[21];

    cudaFuncSetAttribute(fused_kernel, cudaFuncAttributeMaxDynamicSharedMemorySize, SMEM_BYTES);

    prep_all<<<136, 512>>>(pa);
    fused_kernel<<<(p.B + 63) / 64, NT, SMEM_BYTES>>>(p);
}